// round 2
// baseline (speedup 1.0000x reference)
#include <cuda_runtime.h>
#include <math.h>

// Problem dims
#define T_STEPS 8
#define N_PED   2048
#define H_DIM   128
#define D_IN    64
#define G4H     512   // 4*H
#define N_GRP   64
#define GRP_N   32
#define DD_DIM  64
#define NH      4

// ---------------- scratch (device globals; no allocation) ----------------
__device__ __align__(16) float d_x [T_STEPS * N_PED * D_IN];   // embedded input
__device__ __align__(16) float d_xw[T_STEPS * N_PED * G4H];    // x @ W_ih^T + b
__device__ __align__(16) float d_g [N_PED * G4H];              // h @ W_hh^T
__device__ __align__(16) float d_h [N_PED * H_DIM];
__device__ __align__(16) float d_c [N_PED * H_DIM];
__device__ __align__(16) float d_uv[2 * NH * H_DIM];           // u then v
__device__ __align__(16) float d_m [NH * N_PED * H_DIM];       // attention-pooled features

// ---------------- embedding: x = relu(obs @ W_emb + b_emb) ----------------
__global__ void embed_kernel(const float* __restrict__ obs,
                             const float* __restrict__ W_emb,
                             const float* __restrict__ b_emb)
{
    int idx = blockIdx.x * blockDim.x + threadIdx.x;   // < T*N*64
    int row = idx >> 6;
    int c   = idx & 63;
    float o0 = obs[row * 2 + 0];
    float o1 = obs[row * 2 + 1];
    float v  = fmaf(o0, W_emb[c], fmaf(o1, W_emb[64 + c], b_emb[c]));
    d_x[idx] = fmaxf(v, 0.f);
}

// ---------------- generic fp32 GEMM: C[M,N] = A[M,K] @ B[N,K]^T + bias ----------------
// M % 64 == 0, N % 64 == 0, K % 16 == 0
__global__ __launch_bounds__(256) void gemm_nt(
    const float* __restrict__ A, const float* __restrict__ B,
    float* __restrict__ C, int M, int N, int K,
    const float* __restrict__ bias1, const float* __restrict__ bias2)
{
    __shared__ float As[16][64];
    __shared__ float Bs[16][64];
    int tid = threadIdx.x;
    int m0 = blockIdx.y * 64;
    int n0 = blockIdx.x * 64;
    int tx = tid & 15, ty = tid >> 4;

    float acc[4][4];
#pragma unroll
    for (int r = 0; r < 4; r++)
#pragma unroll
        for (int e = 0; e < 4; e++) acc[r][e] = 0.f;

    int lrow = tid >> 2;        // 0..63
    int lk4  = (tid & 3) * 4;   // 0,4,8,12

    for (int k0 = 0; k0 < K; k0 += 16) {
        float4 av = *(const float4*)&A[(size_t)(m0 + lrow) * K + k0 + lk4];
        float4 bv = *(const float4*)&B[(size_t)(n0 + lrow) * K + k0 + lk4];
        As[lk4 + 0][lrow] = av.x; As[lk4 + 1][lrow] = av.y;
        As[lk4 + 2][lrow] = av.z; As[lk4 + 3][lrow] = av.w;
        Bs[lk4 + 0][lrow] = bv.x; Bs[lk4 + 1][lrow] = bv.y;
        Bs[lk4 + 2][lrow] = bv.z; Bs[lk4 + 3][lrow] = bv.w;
        __syncthreads();
#pragma unroll
        for (int kk = 0; kk < 16; kk++) {
            float4 a = *(const float4*)&As[kk][ty * 4];
            float4 b = *(const float4*)&Bs[kk][tx * 4];
            acc[0][0] = fmaf(a.x, b.x, acc[0][0]); acc[0][1] = fmaf(a.x, b.y, acc[0][1]);
            acc[0][2] = fmaf(a.x, b.z, acc[0][2]); acc[0][3] = fmaf(a.x, b.w, acc[0][3]);
            acc[1][0] = fmaf(a.y, b.x, acc[1][0]); acc[1][1] = fmaf(a.y, b.y, acc[1][1]);
            acc[1][2] = fmaf(a.y, b.z, acc[1][2]); acc[1][3] = fmaf(a.y, b.w, acc[1][3]);
            acc[2][0] = fmaf(a.z, b.x, acc[2][0]); acc[2][1] = fmaf(a.z, b.y, acc[2][1]);
            acc[2][2] = fmaf(a.z, b.z, acc[2][2]); acc[2][3] = fmaf(a.z, b.w, acc[2][3]);
            acc[3][0] = fmaf(a.w, b.x, acc[3][0]); acc[3][1] = fmaf(a.w, b.y, acc[3][1]);
            acc[3][2] = fmaf(a.w, b.z, acc[3][2]); acc[3][3] = fmaf(a.w, b.w, acc[3][3]);
        }
        __syncthreads();
    }

    float bsum[4];
#pragma unroll
    for (int e = 0; e < 4; e++) {
        int n = n0 + tx * 4 + e;
        float b = 0.f;
        if (bias1) b += bias1[n];
        if (bias2) b += bias2[n];
        bsum[e] = b;
    }
#pragma unroll
    for (int r = 0; r < 4; r++) {
        int m = m0 + ty * 4 + r;
#pragma unroll
        for (int e = 0; e < 4; e++)
            C[(size_t)m * N + n0 + tx * 4 + e] = acc[r][e] + bsum[e];
    }
}

// ---------------- LSTM pointwise epilogue ----------------
__device__ __forceinline__ float sigf(float x) { return 1.f / (1.f + expf(-x)); }

__global__ void lstm_epi(const float* __restrict__ xw_t)
{
    int idx = blockIdx.x * blockDim.x + threadIdx.x;  // < N*H
    int p = idx >> 7;
    int c = idx & 127;
    const float* gp = d_g + (size_t)p * G4H;
    const float* xp = xw_t + (size_t)p * G4H;
    float gi = xp[c]       + gp[c];
    float gf = xp[c + 128] + gp[c + 128];
    float gg = xp[c + 256] + gp[c + 256];
    float go = xp[c + 384] + gp[c + 384];
    float cn = sigf(gf) * d_c[idx] + sigf(gi) * tanhf(gg);
    d_c[idx] = cn;
    d_h[idx] = sigf(go) * tanhf(cn);
}

// ---------------- u_h = w_h @ a1, v_h = w_h @ a2 ----------------
__global__ void uv_kernel(const float* __restrict__ gat_w,
                          const float* __restrict__ gat_a)
{
    int h = blockIdx.x;
    int tid = threadIdx.x;            // 0..255
    int c = tid & 127;
    const float* a = gat_a + ((tid < 128) ? 0 : 128);
    const float* w = gat_w + (size_t)h * H_DIM * H_DIM + (size_t)c * H_DIM;
    float s = 0.f;
#pragma unroll 8
    for (int o = 0; o < 128; o++) s = fmaf(w[o], a[o], s);
    d_uv[((tid < 128) ? h : NH + h) * H_DIM + c] = s;
}

// ---------------- GAT main: per (group, row i), 128 threads ----------------
__global__ __launch_bounds__(128) void gat_kernel(
    const float* __restrict__ goal_hidden, const float* __restrict__ goal,
    const float* __restrict__ action,      const float* __restrict__ W_dist,
    const float* __restrict__ b_dist,      const float* __restrict__ W_gate,
    const float* __restrict__ b_gate)
{
    int i = blockIdx.x;       // row within group
    int g = blockIdx.y;       // group
    int tid = threadIdx.x;    // 0..127
    int p = g * GRP_N + i;

    __shared__ float th_sh[GRP_N][H_DIM];     // tanh(ah[j])
    __shared__ float gate_sh[GRP_N][H_DIM];
    __shared__ float r_sh[GRP_N][DD_DIM];
    __shared__ float ahv[H_DIM], ghv[H_DIM];
    __shared__ float pax[GRP_N], pay[GRP_N], pgx[GRP_N], pgy[GRP_N];
    __shared__ float sdot_sh[NH][GRP_N];
    __shared__ float scr[NH][GRP_N + 1];
    __shared__ float alpha_sh[NH][GRP_N + 1];
    __shared__ float hsum[NH][3];             // su, sv, sg

    // P0: loads
    ahv[tid] = d_h[(size_t)p * H_DIM + tid];
    ghv[tid] = goal_hidden[(size_t)p * H_DIM + tid];
    if (tid < GRP_N) {
        int q = g * GRP_N + tid;
        pax[tid] = action[q * 2 + 0]; pay[tid] = action[q * 2 + 1];
        pgx[tid] = goal[q * 2 + 0];   pgy[tid] = goal[q * 2 + 1];
    }
    for (int j = 0; j < GRP_N; j++)
        th_sh[j][tid] = tanhf(d_h[(size_t)(g * GRP_N + j) * H_DIM + tid]);
    __syncthreads();

    // P1: r[j][d] = relu(dist(i,j) @ W_dist + b_dist)
    {
        float aix = pax[i], aiy = pay[i], gix = pgx[i], giy = pgy[i];
        for (int it = 0; it < 16; it++) {
            int idx = tid + 128 * it;
            int j = idx >> 6, d = idx & 63;
            float acc = b_dist[d];
            acc = fmaf(aix, W_dist[0 * 64 + d], acc);
            acc = fmaf(aiy, W_dist[1 * 64 + d], acc);
            acc = fmaf(gix, W_dist[2 * 64 + d], acc);
            acc = fmaf(giy, W_dist[3 * 64 + d], acc);
            acc = fmaf(pax[j], W_dist[4 * 64 + d], acc);
            acc = fmaf(pay[j], W_dist[5 * 64 + d], acc);
            acc = fmaf(pgx[j], W_dist[6 * 64 + d], acc);
            acc = fmaf(pgy[j], W_dist[7 * 64 + d], acc);
            r_sh[j][d] = fmaxf(acc, 0.f);
        }
    }
    __syncthreads();

    // P2: gate[j][c=tid] = sigmoid(r[j] @ W_gate[:,c] + b_gate[c])
    {
        float acc[GRP_N];
#pragma unroll
        for (int j = 0; j < GRP_N; j++) acc[j] = 0.f;
        for (int d0 = 0; d0 < DD_DIM; d0 += 8) {
            float w[8];
#pragma unroll
            for (int dd = 0; dd < 8; dd++) w[dd] = W_gate[(d0 + dd) * H_DIM + tid];
#pragma unroll
            for (int j = 0; j < GRP_N; j++) {
#pragma unroll
                for (int dd = 0; dd < 8; dd++)
                    acc[j] = fmaf(r_sh[j][d0 + dd], w[dd], acc[j]);
            }
        }
        float bg = b_gate[tid];
#pragma unroll
        for (int j = 0; j < GRP_N; j++)
            gate_sh[j][tid] = 1.f / (1.f + expf(-(acc[j] + bg)));
    }
    __syncthreads();

    // P3: per-head dots. warp h handles head h.
    {
        int wid = tid >> 5, lane = tid & 31;
        const float* uh = d_uv + wid * H_DIM;
        const float* vh = d_uv + (NH + wid) * H_DIM;
        for (int j = 0; j < GRP_N; j++) {
            float s = 0.f;
#pragma unroll
            for (int cc = lane; cc < H_DIM; cc += 32)
                s = fmaf(gate_sh[j][cc] * th_sh[j][cc], vh[cc], s);
#pragma unroll
            for (int o = 16; o; o >>= 1) s += __shfl_xor_sync(0xffffffffu, s, o);
            if (lane == 0) sdot_sh[wid][j] = s;
        }
        float su = 0.f, sv = 0.f, sg = 0.f;
#pragma unroll
        for (int cc = lane; cc < H_DIM; cc += 32) {
            su = fmaf(ahv[cc], uh[cc], su);
            sv = fmaf(ahv[cc], vh[cc], sv);
            sg = fmaf(ghv[cc], vh[cc], sg);
        }
#pragma unroll
        for (int o = 16; o; o >>= 1) {
            su += __shfl_xor_sync(0xffffffffu, su, o);
            sv += __shfl_xor_sync(0xffffffffu, sv, o);
            sg += __shfl_xor_sync(0xffffffffu, sg, o);
        }
        if (lane == 0) { hsum[wid][0] = su; hsum[wid][1] = sv; hsum[wid][2] = sg; }
    }
    __syncthreads();

    // P4: scores (leaky relu) + softmax over k=0..32 per head
    for (int idx = tid; idx < NH * (GRP_N + 1); idx += 128) {
        int h = idx / (GRP_N + 1), k = idx % (GRP_N + 1);
        float s;
        if (k == 0) s = hsum[h][0] + hsum[h][1];
        else {
            int j = k - 1;
            s = hsum[h][0] + ((j == i) ? hsum[h][2] : sdot_sh[h][j]);
        }
        scr[h][k] = (s >= 0.f) ? s : 0.2f * s;
    }
    __syncthreads();
    if (tid < NH) {
        int h = tid;
        float mx = -1e30f;
        for (int k = 0; k <= GRP_N; k++) mx = fmaxf(mx, scr[h][k]);
        float sum = 0.f;
        for (int k = 0; k <= GRP_N; k++) sum += expf(scr[h][k] - mx);
        float inv = 1.f / sum;
        for (int k = 0; k <= GRP_N; k++) alpha_sh[h][k] = expf(scr[h][k] - mx) * inv;
    }
    __syncthreads();

    // P5: m[h][c] = alpha0*ah[c] + sum_j alpha_{j+1} * goal_action[j][c]
    {
        int c = tid;
        float ahc = ahv[c], ghc = ghv[c];
        for (int h = 0; h < NH; h++) {
            float mv = alpha_sh[h][0] * ahc;
#pragma unroll 8
            for (int j = 0; j < GRP_N; j++) {
                float ga = (j == i) ? ghc : gate_sh[j][c] * th_sh[j][c];
                mv = fmaf(alpha_sh[h][j + 1], ga, mv);
            }
            d_m[((size_t)h * N_PED + p) * H_DIM + c] = mv;
        }
    }
}

// ---------------- final: out = relu(0.25 * sum_h m_h @ w_h) + gat_bias ----------------
__global__ __launch_bounds__(128) void g3_kernel(
    const float* __restrict__ gat_w, const float* __restrict__ gat_bias,
    float* __restrict__ out)
{
    const int TP = 8;
    int p0 = blockIdx.x * TP;
    int tid = threadIdx.x;   // output column c
    __shared__ float m_sh[TP][H_DIM];
    float acc[TP];
#pragma unroll
    for (int r = 0; r < TP; r++) acc[r] = 0.f;

    for (int h = 0; h < NH; h++) {
        __syncthreads();
#pragma unroll
        for (int r = 0; r < TP; r++)
            m_sh[r][tid] = d_m[((size_t)h * N_PED + p0 + r) * H_DIM + tid];
        __syncthreads();
        const float* wh = gat_w + (size_t)h * H_DIM * H_DIM;
        for (int f0 = 0; f0 < H_DIM; f0 += 8) {
            float w[8];
#pragma unroll
            for (int dd = 0; dd < 8; dd++) w[dd] = wh[(f0 + dd) * H_DIM + tid];
#pragma unroll
            for (int r = 0; r < TP; r++) {
#pragma unroll
                for (int dd = 0; dd < 8; dd++)
                    acc[r] = fmaf(m_sh[r][f0 + dd], w[dd], acc[r]);
            }
        }
    }
    float b = gat_bias[tid];
#pragma unroll
    for (int r = 0; r < TP; r++)
        out[(size_t)(p0 + r) * H_DIM + tid] = fmaxf(0.25f * acc[r], 0.f) + b;
}

// ---------------- host ----------------
extern "C" void kernel_launch(void* const* d_in, const int* in_sizes, int n_in,
                              void* d_out, int out_size)
{
    const float* obs         = (const float*)d_in[0];
    const float* goal_hidden = (const float*)d_in[1];
    const float* goal        = (const float*)d_in[2];
    const float* action      = (const float*)d_in[3];
    const float* h0          = (const float*)d_in[4];
    const float* c0          = (const float*)d_in[5];
    const float* W_emb       = (const float*)d_in[6];
    const float* b_emb       = (const float*)d_in[7];
    const float* W_ih        = (const float*)d_in[8];
    const float* W_hh        = (const float*)d_in[9];
    const float* b_ih        = (const float*)d_in[10];
    const float* b_hh        = (const float*)d_in[11];
    const float* W_dist      = (const float*)d_in[12];
    const float* b_dist      = (const float*)d_in[13];
    const float* W_gate      = (const float*)d_in[14];
    const float* b_gate      = (const float*)d_in[15];
    const float* gat_w       = (const float*)d_in[16];
    const float* gat_a       = (const float*)d_in[17];
    const float* gat_bias    = (const float*)d_in[18];
    // d_in[19] = seq_start_end : groups are contiguous blocks of 32 by construction
    float* out = (float*)d_out;

    float *px, *pxw, *pg, *ph, *pc;
    cudaGetSymbolAddress((void**)&px,  d_x);
    cudaGetSymbolAddress((void**)&pxw, d_xw);
    cudaGetSymbolAddress((void**)&pg,  d_g);
    cudaGetSymbolAddress((void**)&ph,  d_h);
    cudaGetSymbolAddress((void**)&pc,  d_c);

    cudaMemcpyAsync(ph, h0, (size_t)N_PED * H_DIM * sizeof(float), cudaMemcpyDeviceToDevice);
    cudaMemcpyAsync(pc, c0, (size_t)N_PED * H_DIM * sizeof(float), cudaMemcpyDeviceToDevice);

    // embedding + input-GEMM precompute for all timesteps
    embed_kernel<<<(T_STEPS * N_PED * D_IN) / 256, 256>>>(obs, W_emb, b_emb);
    gemm_nt<<<dim3(G4H / 64, (T_STEPS * N_PED) / 64), 256>>>(
        px, W_ih, pxw, T_STEPS * N_PED, G4H, D_IN, b_ih, b_hh);

    // sequential LSTM
    for (int t = 0; t < T_STEPS; t++) {
        gemm_nt<<<dim3(G4H / 64, N_PED / 64), 256>>>(
            ph, W_hh, pg, N_PED, G4H, H_DIM, nullptr, nullptr);
        lstm_epi<<<(N_PED * H_DIM) / 256, 256>>>(pxw + (size_t)t * N_PED * G4H);
    }

    // GAT
    uv_kernel<<<NH, 256>>>(gat_w, gat_a);
    gat_kernel<<<dim3(GRP_N, N_GRP), 128>>>(goal_hidden, goal, action,
                                            W_dist, b_dist, W_gate, b_gate);
    g3_kernel<<<N_PED / 8, 128>>>(gat_w, gat_bias, out);
}